// round 13
// baseline (speedup 1.0000x reference)
#include <cuda_runtime.h>
#include <cuda_fp16.h>
#include <cstdint>

#define N_NODES     100000
#define D_FEAT      128
#define N_EDGES_MAX 50008

// fp16 copy of the embedding table (25.6 MB scratch), row = 256 B
__device__ uint4 d_emb_h[(size_t)N_NODES * 16];
// segment start offsets
__device__ int d_seg_start[N_EDGES_MAX + 1];

// ---------------------------------------------------------------------------
// Prep kernel (grid-stride, fused):
//  A) convert emb table f32 -> fp16 (monotone rounding commutes with max;
//     |err| <= 2^-11 < 1e-3 threshold). f32 reads use __ldcs (evict-first)
//     so the fp16 table owns L2 when the gather starts.
//  B) run-boundary detection on sorted segment_ids
// Ends with griddepcontrol.launch_dependents so the PDL-launched gather can
// overlap its launch ramp with prep's tail.
// ---------------------------------------------------------------------------
__global__ void prep_kernel(const float4* __restrict__ emb4,   // [N_NODES*32]
                            const int* __restrict__ seg_ids,
                            int flat, int n_edges) {
    int gid    = blockIdx.x * blockDim.x + threadIdx.x;
    int stride = gridDim.x * blockDim.x;
    int lane   = threadIdx.x & 31;

    // A: 8 floats -> 8 halves (16B store) per iteration
    const int n8 = N_NODES * D_FEAT / 8;
    for (int i = gid; i < n8; i += stride) {
        float4 a = __ldcs(&emb4[2 * i]);
        float4 b = __ldcs(&emb4[2 * i + 1]);
        half2 h0 = __floats2half2_rn(a.x, a.y);
        half2 h1 = __floats2half2_rn(a.z, a.w);
        half2 h2 = __floats2half2_rn(b.x, b.y);
        half2 h3 = __floats2half2_rn(b.z, b.w);
        uint4 u;
        u.x = *reinterpret_cast<uint32_t*>(&h0);
        u.y = *reinterpret_cast<uint32_t*>(&h1);
        u.z = *reinterpret_cast<uint32_t*>(&h2);
        u.w = *reinterpret_cast<uint32_t*>(&h3);
        d_emb_h[i] = u;
    }

    // B: boundaries; one load per element, neighbor via shfl
    for (int i = gid; i < flat; i += stride) {
        int cur  = __ldg(&seg_ids[i]);
        int prev = __shfl_up_sync(0xffffffffu, cur, 1);
        if (lane == 0)
            prev = (i == 0) ? -1 : __ldg(&seg_ids[i - 1]);
        for (int e = prev + 1; e <= cur; e++)
            d_seg_start[e] = i;
        if (i == flat - 1) {
            for (int e = cur + 1; e <= n_edges; e++)
                d_seg_start[e] = flat;
        }
    }

    // signal dependents (all writes above complete for this thread)
    asm volatile("griddepcontrol.launch_dependents;" ::: "memory");
}

// ---------------------------------------------------------------------------
// Gather kernel: warp-per-segment, TWO members per LDG (lanes 0-15 member A,
// lanes 16-31 member B in one LDG.128 over the 256B fp16 row). Uniform trip
// count; clamped index prefetch makes lanes >= cnt hold valid (idempotent)
// offsets so no per-iteration clamp is needed. Output uses streaming stores.
// PDL: launched with programmatic serialization; waits on griddepcontrol
// before touching prep's outputs. Sits on the chip LTS byte roofline.
// ---------------------------------------------------------------------------
__global__ void __launch_bounds__(256)
seg_max_kernel(const int* __restrict__ node_idx,
               float4* __restrict__ out,            // [n_edges * 32] float4
               int n_edges) {
    // block until prep's memory is visible (PDL)
    asm volatile("griddepcontrol.wait;" ::: "memory");

    int gwarp = (blockIdx.x * blockDim.x + threadIdx.x) >> 5;
    int lane  = threadIdx.x & 31;
    if (gwarp >= n_edges) return;

    int start = d_seg_start[gwarp];
    int end   = d_seg_start[gwarp + 1];

    int fl = lane & 15;          // feature chunk: features [8*fl, 8*fl+8)
    int hw = lane >> 4;          // 0: member A, 1: member B
    float4* oslot = out + (size_t)gwarp * 32 + 2 * fl + hw;

    if (start >= end) {                       // empty segment -> zeros
        __stwt(oslot, make_float4(0.f, 0.f, 0.f, 0.f));
        return;
    }

    const half2 NEG2 = __half2half2(__ushort_as_half((unsigned short)0xFC00));
    half2 a0 = NEG2, a1 = NEG2, a2 = NEG2, a3 = NEG2;

    const char* embl = reinterpret_cast<const char*>(d_emb_h) + fl * 16;
    int last = end - 1;

    for (int base = start; base < end; base += 32) {
        int li = base + lane;
        // coalesced clamped index fetch, pre-scaled to BYTE row offset (<<8)
        int off_l = __ldg(&node_idx[li <= last ? li : last]) << 8;
        int cnt = end - base;
        if (cnt > 32) cnt = 32;
        int npair = (cnt + 1) >> 1;           // uniform across the warp

        #pragma unroll 8
        for (int j = 0; j < npair; j++) {
            int src = 2 * j + hw;             // <= 31 always; lanes>=cnt valid
            int off = __shfl_sync(0xffffffffu, off_l, src);
            uint4 v = __ldg(reinterpret_cast<const uint4*>(embl + off));
            a0 = __hmax2(a0, *reinterpret_cast<half2*>(&v.x));
            a1 = __hmax2(a1, *reinterpret_cast<half2*>(&v.y));
            a2 = __hmax2(a2, *reinterpret_cast<half2*>(&v.z));
            a3 = __hmax2(a3, *reinterpret_cast<half2*>(&v.w));
        }
    }

    // merge the two half-warp accumulators (lane <-> lane^16)
    #define MERGE(r) { \
        uint32_t u = *reinterpret_cast<uint32_t*>(&r); \
        uint32_t p = __shfl_xor_sync(0xffffffffu, u, 16); \
        r = __hmax2(r, *reinterpret_cast<half2*>(&p)); }
    MERGE(a0) MERGE(a1) MERGE(a2) MERGE(a3)
    #undef MERGE

    half2 r0 = hw ? a2 : a0;
    half2 r1 = hw ? a3 : a1;
    float4 o;
    o.x = __half2float(__low2half(r0));
    o.y = __half2float(__high2half(r0));
    o.z = __half2float(__low2half(r1));
    o.w = __half2float(__high2half(r1));
    __stwt(oslot, o);                         // streaming: don't pollute L2
}

// ---------------------------------------------------------------------------
// Launch (gather via PDL so its launch ramp overlaps prep's tail)
// ---------------------------------------------------------------------------
extern "C" void kernel_launch(void* const* d_in, const int* in_sizes, int n_in,
                              void* d_out, int out_size) {
    const float4* emb4     = (const float4*)d_in[0];
    const int*    node_idx = (const int*)d_in[1];
    const int*    seg_ids  = (const int*)d_in[2];
    float4*       out      = (float4*)d_out;

    int flat    = in_sizes[1];            // 1,600,000
    int n_edges = out_size / D_FEAT;      // 50,000

    {
        int threads = 256;
        int blocks  = 8192;               // grid-stride over both phases
        prep_kernel<<<blocks, threads>>>(emb4, seg_ids, flat, n_edges);
    }
    {
        cudaLaunchConfig_t cfg = {};
        cfg.gridDim  = dim3((unsigned)((n_edges * 32 + 255) / 256));
        cfg.blockDim = dim3(256);
        cfg.dynamicSmemBytes = 0;
        cfg.stream = 0;                    // same (legacy default) stream

        cudaLaunchAttribute attr[1];
        attr[0].id = cudaLaunchAttributeProgrammaticStreamSerialization;
        attr[0].val.programmaticStreamSerializationAllowed = 1;
        cfg.attrs    = attr;
        cfg.numAttrs = 1;

        cudaLaunchKernelEx(&cfg, seg_max_kernel, node_idx, out, n_edges);
    }
}

// round 14
// speedup vs baseline: 1.0598x; 1.0598x over previous
#include <cuda_runtime.h>
#include <cuda_fp16.h>
#include <cstdint>

#define N_NODES     100000
#define D_FEAT      128
#define N_EDGES_MAX 50008

// fp16 copy of the embedding table (25.6 MB scratch), row = 256 B
__device__ uint4 d_emb_h[(size_t)N_NODES * 16];
// segment start offsets
__device__ int d_seg_start[N_EDGES_MAX + 1];

// ---------------------------------------------------------------------------
// Prep kernel (grid-stride, fused):
//  A) convert emb table f32 -> fp16 (monotone rounding commutes with max;
//     |err| <= 2^-11 < 1e-3 threshold). f32 reads use __ldcs (evict-first)
//     so the fp16 table owns L2 when the gather starts.
//  B) run-boundary detection on sorted segment_ids
// ---------------------------------------------------------------------------
__global__ void prep_kernel(const float4* __restrict__ emb4,   // [N_NODES*32]
                            const int* __restrict__ seg_ids,
                            int flat, int n_edges) {
    int gid    = blockIdx.x * blockDim.x + threadIdx.x;
    int stride = gridDim.x * blockDim.x;
    int lane   = threadIdx.x & 31;

    // A: 8 floats -> 8 halves (16B store) per iteration
    const int n8 = N_NODES * D_FEAT / 8;
    for (int i = gid; i < n8; i += stride) {
        float4 a = __ldcs(&emb4[2 * i]);
        float4 b = __ldcs(&emb4[2 * i + 1]);
        half2 h0 = __floats2half2_rn(a.x, a.y);
        half2 h1 = __floats2half2_rn(a.z, a.w);
        half2 h2 = __floats2half2_rn(b.x, b.y);
        half2 h3 = __floats2half2_rn(b.z, b.w);
        uint4 u;
        u.x = *reinterpret_cast<uint32_t*>(&h0);
        u.y = *reinterpret_cast<uint32_t*>(&h1);
        u.z = *reinterpret_cast<uint32_t*>(&h2);
        u.w = *reinterpret_cast<uint32_t*>(&h3);
        d_emb_h[i] = u;
    }

    // B: boundaries; one load per element, neighbor via shfl
    for (int i = gid; i < flat; i += stride) {
        int cur  = __ldg(&seg_ids[i]);
        int prev = __shfl_up_sync(0xffffffffu, cur, 1);
        if (lane == 0)
            prev = (i == 0) ? -1 : __ldg(&seg_ids[i - 1]);
        for (int e = prev + 1; e <= cur; e++)
            d_seg_start[e] = i;
        if (i == flat - 1) {
            for (int e = cur + 1; e <= n_edges; e++)
                d_seg_start[e] = flat;
        }
    }
}

// ---------------------------------------------------------------------------
// Gather kernel: warp-per-segment, TWO members per LDG (lanes 0-15 member A,
// lanes 16-31 member B in one LDG.128 over the 256B fp16 row). Uniform trip
// count; clamped index prefetch makes lanes >= cnt hold valid (idempotent)
// offsets so no per-iteration clamp is needed. Output uses streaming stores.
// Sits on the chip LTS byte roofline (~440MB / ~6300 B/cyc).
// ---------------------------------------------------------------------------
__global__ void __launch_bounds__(256)
seg_max_kernel(const int* __restrict__ node_idx,
               float4* __restrict__ out,            // [n_edges * 32] float4
               int n_edges) {
    int gwarp = (blockIdx.x * blockDim.x + threadIdx.x) >> 5;
    int lane  = threadIdx.x & 31;
    if (gwarp >= n_edges) return;

    int start = d_seg_start[gwarp];
    int end   = d_seg_start[gwarp + 1];

    int fl = lane & 15;          // feature chunk: features [8*fl, 8*fl+8)
    int hw = lane >> 4;          // 0: member A, 1: member B
    float4* oslot = out + (size_t)gwarp * 32 + 2 * fl + hw;

    if (start >= end) {                       // empty segment -> zeros
        __stwt(oslot, make_float4(0.f, 0.f, 0.f, 0.f));
        return;
    }

    const half2 NEG2 = __half2half2(__ushort_as_half((unsigned short)0xFC00));
    half2 a0 = NEG2, a1 = NEG2, a2 = NEG2, a3 = NEG2;

    const char* embl = reinterpret_cast<const char*>(d_emb_h) + fl * 16;
    int last = end - 1;

    for (int base = start; base < end; base += 32) {
        int li = base + lane;
        // coalesced clamped index fetch, pre-scaled to BYTE row offset (<<8)
        int off_l = __ldg(&node_idx[li <= last ? li : last]) << 8;
        int cnt = end - base;
        if (cnt > 32) cnt = 32;
        int npair = (cnt + 1) >> 1;           // uniform across the warp

        #pragma unroll 4
        for (int j = 0; j < npair; j++) {
            int src = 2 * j + hw;             // <= 31 always; lanes>=cnt valid
            int off = __shfl_sync(0xffffffffu, off_l, src);
            uint4 v = __ldg(reinterpret_cast<const uint4*>(embl + off));
            a0 = __hmax2(a0, *reinterpret_cast<half2*>(&v.x));
            a1 = __hmax2(a1, *reinterpret_cast<half2*>(&v.y));
            a2 = __hmax2(a2, *reinterpret_cast<half2*>(&v.z));
            a3 = __hmax2(a3, *reinterpret_cast<half2*>(&v.w));
        }
    }

    // merge the two half-warp accumulators (lane <-> lane^16)
    #define MERGE(r) { \
        uint32_t u = *reinterpret_cast<uint32_t*>(&r); \
        uint32_t p = __shfl_xor_sync(0xffffffffu, u, 16); \
        r = __hmax2(r, *reinterpret_cast<half2*>(&p)); }
    MERGE(a0) MERGE(a1) MERGE(a2) MERGE(a3)
    #undef MERGE

    half2 r0 = hw ? a2 : a0;
    half2 r1 = hw ? a3 : a1;
    float4 o;
    o.x = __half2float(__low2half(r0));
    o.y = __half2float(__high2half(r0));
    o.z = __half2float(__low2half(r1));
    o.w = __half2float(__high2half(r1));
    __stwt(oslot, o);                         // streaming: don't pollute L2
}

// ---------------------------------------------------------------------------
// Launch
// ---------------------------------------------------------------------------
extern "C" void kernel_launch(void* const* d_in, const int* in_sizes, int n_in,
                              void* d_out, int out_size) {
    const float4* emb4     = (const float4*)d_in[0];
    const int*    node_idx = (const int*)d_in[1];
    const int*    seg_ids  = (const int*)d_in[2];
    float4*       out      = (float4*)d_out;

    int flat    = in_sizes[1];            // 1,600,000
    int n_edges = out_size / D_FEAT;      // 50,000

    {
        int threads = 256;
        int blocks  = 8192;               // grid-stride over both phases
        prep_kernel<<<blocks, threads>>>(emb4, seg_ids, flat, n_edges);
    }
    {
        int threads = 256;                // 8 warps = 8 segments / block
        int blocks  = (n_edges * 32 + threads - 1) / threads;
        seg_max_kernel<<<blocks, threads>>>(node_idx, out, n_edges);
    }
}